// round 9
// baseline (speedup 1.0000x reference)
#include <cuda_runtime.h>
#include <cuda_fp16.h>
#include <math.h>
#include <stdint.h>

#define BB 2
#define NSEQ 2048
#define DIMC 768
#define NH 12
#define DH 64
#define BHN (BB*NH)
#define MROWS (BB*NSEQ)
// 0.125 * log2(e): softmax done in base-2
#define QSCALE_L2E 0.18033688011112042f
// static softmax offset: |scores| <= 64*0.125*log2e = 11.54 < 12 (rmsnorm + rotation)
#define SOFF 12.0f

// ---------------- scratch (static device globals; no allocation) -------------
__device__ float  g_qkv[(size_t)MROWS * 3 * DIMC];          // fp32 qkv
__device__ __half g_xh[(size_t)MROWS * DIMC];
__device__ __half g_qkvwh[(size_t)3 * DIMC * DIMC];
__device__ __half g_projwh[(size_t)DIMC * DIMC];
__device__ __half g_atth[(size_t)MROWS * DIMC];
__device__ __half g_q[(size_t)BHN * NSEQ * DH];
__device__ __half g_k[(size_t)BHN * NSEQ * DH];
__device__ __half g_v[(size_t)BHN * NSEQ * DH];

// ---------------- helpers ---------------------------------------------------
__device__ __forceinline__ uint32_t h2u(float a, float b) {
    __half2 h = __floats2half2_rn(a, b);
    return *reinterpret_cast<uint32_t*>(&h);
}
__device__ __forceinline__ uint32_t smaddr(const void* p) {
    return (uint32_t)__cvta_generic_to_shared(p);
}
__device__ __forceinline__ void cp16(void* dst, const void* src) {
    asm volatile("cp.async.cg.shared.global [%0], [%1], 16;"
                 :: "r"(smaddr(dst)), "l"(src));
}
#define CP_COMMIT() asm volatile("cp.async.commit_group;")
#define CP_WAIT(n)  asm volatile("cp.async.wait_group %0;" :: "n"(n))

__device__ __forceinline__ void ldsm4(uint32_t& r0, uint32_t& r1,
                                      uint32_t& r2, uint32_t& r3, const void* p) {
    asm volatile("ldmatrix.sync.aligned.m8n8.x4.shared.b16 {%0,%1,%2,%3}, [%4];"
                 : "=r"(r0), "=r"(r1), "=r"(r2), "=r"(r3) : "r"(smaddr(p)));
}
__device__ __forceinline__ void ldsm4t(uint32_t& r0, uint32_t& r1,
                                       uint32_t& r2, uint32_t& r3, const void* p) {
    asm volatile("ldmatrix.sync.aligned.m8n8.x4.trans.shared.b16 {%0,%1,%2,%3}, [%4];"
                 : "=r"(r0), "=r"(r1), "=r"(r2), "=r"(r3) : "r"(smaddr(p)));
}
__device__ __forceinline__ void mma_h(float4& d,
    uint32_t a0, uint32_t a1, uint32_t a2, uint32_t a3,
    uint32_t b0, uint32_t b1)
{
    asm volatile(
        "mma.sync.aligned.m16n8k16.row.col.f32.f16.f16.f32 "
        "{%0,%1,%2,%3}, {%4,%5,%6,%7}, {%8,%9}, {%0,%1,%2,%3};"
        : "+f"(d.x), "+f"(d.y), "+f"(d.z), "+f"(d.w)
        : "r"(a0), "r"(a1), "r"(a2), "r"(a3), "r"(b0), "r"(b1));
}

// exp2 via FMA polynomial + exponent splice — no MUFU in the hot loop.
__device__ __forceinline__ float exp2_fast(float t) {
    t = fmaxf(t, -120.0f);
    float z = t + 12582912.0f;
    int  i = __float_as_int(z) - 0x4B400000;
    float f = t - (z - 12582912.0f);
    float p = 1.3333558e-3f;
    p = fmaf(p, f, 9.6181291e-3f);
    p = fmaf(p, f, 5.5504109e-2f);
    p = fmaf(p, f, 2.4022651e-1f);
    p = fmaf(p, f, 6.9314718e-1f);
    p = fmaf(p, f, 1.0f);
    return __int_as_float((i + 127) << 23) * p;
}

// ---------------- fp32 -> fp16 convert --------------------------------------
__global__ void __launch_bounds__(256) f2h_kernel(const float* __restrict__ in,
                                                  __half* __restrict__ out, int n4)
{
    int i = blockIdx.x * blockDim.x + threadIdx.x;
    if (i >= n4) return;
    float4 v = *(const float4*)(in + (size_t)i * 4);
    uint2 o;
    o.x = h2u(v.x, v.y);
    o.y = h2u(v.z, v.w);
    *(uint2*)(out + (size_t)i * 4) = o;
}

// ---------------- fp16 GEMM: C[m][n] = sum_k A[m][k] * W[n][k] (+bias) ------
// CTA tile 128x256, BK=32, 256 threads (8 warps, 2m x 4n), warp tile 64x64.
// 3-stage cp.async pipeline, one barrier per iteration, ldmatrix fragments.
#define GP 40
#define GATILE (128 * GP)
#define GBTILE (256 * GP)
#define GEMM_SMEM ((3 * GATILE + 3 * GBTILE) * (int)sizeof(__half))   // 92160
template<bool BIAS>
__global__ void __launch_bounds__(256) gemm_h(
    const __half* __restrict__ A, const __half* __restrict__ W,
    const float* __restrict__ bias, float* __restrict__ C,
    int M, int N, int K)
{
    extern __shared__ __half gsm[];
    __half* As = gsm;                  // 3 stages x GATILE
    __half* Ws = gsm + 3 * GATILE;     // 3 stages x GBTILE

    const int tid = threadIdx.x;
    const int lane = tid & 31, wid = tid >> 5;
    const int g = lane >> 2, tg = lane & 3;
    const int wm = (wid & 1) * 64;
    const int wn = (wid >> 1) * 64;
    const int mtile = blockIdx.y * 128, ntile = blockIdx.x * 256;

    const int ldr = tid >> 2;            // 0..63
    const int ldc = (tid & 3) * 8;       // 0,8,16,24

    auto issue = [&](int k0, int st) {
#pragma unroll
        for (int i = 0; i < 2; i++) {      // A: 128 rows
            int r = ldr + i * 64;
            cp16(&As[st * GATILE + r * GP + ldc], A + (size_t)(mtile + r) * K + k0 + ldc);
        }
#pragma unroll
        for (int i = 0; i < 4; i++) {      // B: 256 rows
            int r = ldr + i * 64;
            cp16(&Ws[st * GBTILE + r * GP + ldc], W + (size_t)(ntile + r) * K + k0 + ldc);
        }
        CP_COMMIT();
    };

    issue(0, 0);
    issue(32, 1);

    float4 acc[4][8];
#pragma unroll
    for (int mt = 0; mt < 4; mt++)
#pragma unroll
        for (int nt = 0; nt < 8; nt++) acc[mt][nt] = make_float4(0.f, 0.f, 0.f, 0.f);

    const int NIT = K / 32;
    const int arow = (lane & 15);
    const int acol = ((lane >> 4) & 1) * 8;
    const int brow = ((lane & 16) >> 1) + (lane & 7);
    const int bcol = (lane & 8);

    int st = 0;
    for (int it = 0; it < NIT; it++) {
        if (it == NIT - 1) { CP_WAIT(0); } else { CP_WAIT(1); }
        __syncthreads();
        if (it + 2 < NIT) issue((it + 2) * 32, (st + 2) % 3);
        const __half* as = As + st * GATILE;
        const __half* ws = Ws + st * GBTILE;
#pragma unroll
        for (int ks = 0; ks < 2; ks++) {
            uint32_t af[4][4], bf[8][2];
#pragma unroll
            for (int mt = 0; mt < 4; mt++)
                ldsm4(af[mt][0], af[mt][1], af[mt][2], af[mt][3],
                      &as[(wm + mt * 16 + arow) * GP + ks * 16 + acol]);
#pragma unroll
            for (int p = 0; p < 4; p++)
                ldsm4(bf[2 * p][0], bf[2 * p][1], bf[2 * p + 1][0], bf[2 * p + 1][1],
                      &ws[(wn + p * 16 + brow) * GP + ks * 16 + bcol]);
#pragma unroll
            for (int mt = 0; mt < 4; mt++)
#pragma unroll
                for (int nt = 0; nt < 8; nt++)
                    mma_h(acc[mt][nt], af[mt][0], af[mt][1], af[mt][2], af[mt][3],
                          bf[nt][0], bf[nt][1]);
        }
        st = (st + 1) % 3;
    }

#pragma unroll
    for (int mt = 0; mt < 4; mt++) {
        int r0 = mtile + wm + mt * 16 + g;
#pragma unroll
        for (int nt = 0; nt < 8; nt++) {
            int col = ntile + wn + nt * 8 + 2 * tg;
            float4 v = acc[mt][nt];
            float b0v = 0.f, b1v = 0.f;
            if (BIAS) { b0v = bias[col]; b1v = bias[col + 1]; }
            float2 t0 = {v.x + b0v, v.y + b1v};
            float2 t1 = {v.z + b0v, v.w + b1v};
            *(float2*)(C + (size_t)r0 * N + col) = t0;
            *(float2*)(C + (size_t)(r0 + 8) * N + col) = t1;
        }
    }
}

// -------- fused rmsnorm + 3D RoPE + q-scale(log2e) + fp16 + transpose -------
__global__ void __launch_bounds__(256) prep_kernel(
    const float* __restrict__ qkv, const float* __restrict__ positions,
    const float* __restrict__ qn_w, const float* __restrict__ kn_w,
    __half* __restrict__ qT, __half* __restrict__ kT, __half* __restrict__ vT)
{
    int gwarp = (blockIdx.x * blockDim.x + threadIdx.x) >> 5;
    int lane  = threadIdx.x & 31;
    if (gwarp >= MROWS * NH) return;
    int h = gwarp % NH;
    int m = gwarp / NH;
    int b = m / NSEQ;
    int t = m % NSEQ;

    const float* row = qkv + (size_t)m * (3 * DIMC) + h * DH;
    float2 q = *(const float2*)(row + 2 * lane);
    float2 k = *(const float2*)(row + DIMC + 2 * lane);
    float2 v = *(const float2*)(row + 2 * DIMC + 2 * lane);

    float sq = q.x * q.x + q.y * q.y;
    float sk = k.x * k.x + k.y * k.y;
#pragma unroll
    for (int off = 16; off; off >>= 1) {
        sq += __shfl_xor_sync(0xffffffffu, sq, off);
        sk += __shfl_xor_sync(0xffffffffu, sk, off);
    }
    float rq = rsqrtf(sq * (1.0f / 64.0f) + 1e-6f);
    float rk = rsqrtf(sk * (1.0f / 64.0f) + 1e-6f);
    float2 wq = *(const float2*)(qn_w + 2 * lane);
    float2 wk = *(const float2*)(kn_w + 2 * lane);
    q.x *= rq * wq.x; q.y *= rq * wq.y;
    k.x *= rk * wk.x; k.y *= rk * wk.y;

    if (lane < 30) {                   // rope pairs: first 60 dims
        int p = lane / 10;
        int f = lane % 10;
        float pos  = positions[(size_t)m * 3 + p];
        float freq = __expf(-0.92103403719761836f * (float)f);  // 10000^(-f/10)
        float ang  = pos * freq;
        float s, c;
        __sincosf(ang, &s, &c);
        float qe = q.x * c - q.y * s, qo = q.x * s + q.y * c;
        float ke = k.x * c - k.y * s, ko = k.x * s + k.y * c;
        q.x = qe; q.y = qo; k.x = ke; k.y = ko;
    }
    q.x *= QSCALE_L2E; q.y *= QSCALE_L2E;

    size_t o = ((size_t)(b * NH + h) * NSEQ + t) * DH + 2 * lane;
    *(uint32_t*)(qT + o) = h2u(q.x, q.y);
    *(uint32_t*)(kT + o) = h2u(k.x, k.y);
    *(uint32_t*)(vT + o) = h2u(v.x, v.y);
}

// ---------------- fp16 flash-attention (static-offset base-2 softmax) -------
// 256 threads (8 warps); warp owns 16 query rows. Br=128, Bc=64, DH=64.
// Scores are bounded (rmsnorm -> |s| <= 11.54 base-2), so softmax uses a fixed
// offset: no running max, no correction factors, no per-iter reductions.
#define AP 72
#define KVTILE (64 * AP)
__global__ void __launch_bounds__(256) attn_h(
    const __half* __restrict__ qT, const __half* __restrict__ kT,
    const __half* __restrict__ vT, __half* __restrict__ outh)
{
    extern __shared__ __half asm_[];
    __half* Qs = asm_;                    // 128 x AP
    __half* Ks = asm_ + 128 * AP;         // 3 stages x 64 x AP
    __half* Vs = Ks + 3 * KVTILE;         // 3 stages x 64 x AP

    const int tid = threadIdx.x, lane = tid & 31, w = tid >> 5;
    const int g = lane >> 2, tg = lane & 3;
    const int qt = blockIdx.x, bh = blockIdx.y;

    auto issue_kv = [&](int kc, int st) {
        const __half* kb = kT + ((size_t)bh * NSEQ + kc * 64) * DH;
        const __half* vb = vT + ((size_t)bh * NSEQ + kc * 64) * DH;
#pragma unroll
        for (int i = 0; i < 2; i++) {
            int idx = tid + i * 256;
            int r = idx >> 3, c = (idx & 7) * 8;
            cp16(&Ks[st * KVTILE + r * AP + c], kb + r * 64 + c);
            cp16(&Vs[st * KVTILE + r * AP + c], vb + r * 64 + c);
        }
        CP_COMMIT();
    };

    const __half* qb = qT + ((size_t)bh * NSEQ + qt * 128) * DH;
#pragma unroll
    for (int i = 0; i < 4; i++) {
        int idx = tid + i * 256;
        int r = idx >> 3, c = (idx & 7) * 8;
        *(uint4*)&Qs[r * AP + c] = *(const uint4*)(qb + r * 64 + c);
    }

    issue_kv(0, 0);
    issue_kv(1, 1);
    __syncthreads();

    const int arow = (lane & 15);
    const int acol = ((lane >> 4) & 1) * 8;
    const int brow = ((lane & 16) >> 1) + (lane & 7);
    const int bcol = (lane & 8);

    uint32_t qa[4][4];
#pragma unroll
    for (int kt = 0; kt < 4; kt++)
        ldsm4(qa[kt][0], qa[kt][1], qa[kt][2], qa[kt][3],
              &Qs[(w * 16 + arow) * AP + kt * 16 + acol]);

    float4 accO[8];
#pragma unroll
    for (int nt = 0; nt < 8; nt++) accO[nt] = make_float4(0.f, 0.f, 0.f, 0.f);
    float l0 = 0.f, l1 = 0.f;

    int st = 0;
    for (int kc = 0; kc < 32; kc++) {
        if (kc == 31) { CP_WAIT(0); } else { CP_WAIT(1); }
        __syncthreads();
        if (kc + 2 < 32) issue_kv(kc + 2, (st + 2) % 3);
        const __half* ks = Ks + st * KVTILE;
        const __half* vs = Vs + st * KVTILE;

        // ---- S = Q @ K^T ----
        float4 s[8];
#pragma unroll
        for (int nt = 0; nt < 8; nt++) s[nt] = make_float4(0.f, 0.f, 0.f, 0.f);
#pragma unroll
        for (int kt = 0; kt < 4; kt++) {
            uint32_t kb[8][2];
#pragma unroll
            for (int p = 0; p < 4; p++)
                ldsm4(kb[2 * p][0], kb[2 * p][1], kb[2 * p + 1][0], kb[2 * p + 1][1],
                      &ks[(p * 16 + brow) * AP + kt * 16 + bcol]);
#pragma unroll
            for (int nt = 0; nt < 8; nt++)
                mma_h(s[nt], qa[kt][0], qa[kt][1], qa[kt][2], qa[kt][3],
                      kb[nt][0], kb[nt][1]);
        }

        // ---- static-offset softmax: p = 2^(s - SOFF) ----
        uint32_t pa[4][4];
#pragma unroll
        for (int nt = 0; nt < 8; nt++) {
            s[nt].x = exp2_fast(s[nt].x - SOFF);
            s[nt].y = exp2_fast(s[nt].y - SOFF);
            s[nt].z = exp2_fast(s[nt].z - SOFF);
            s[nt].w = exp2_fast(s[nt].w - SOFF);
            l0 += s[nt].x + s[nt].y;
            l1 += s[nt].z + s[nt].w;
        }
#pragma unroll
        for (int j = 0; j < 4; j++) {
            pa[j][0] = h2u(s[2 * j].x,     s[2 * j].y);
            pa[j][1] = h2u(s[2 * j].z,     s[2 * j].w);
            pa[j][2] = h2u(s[2 * j + 1].x, s[2 * j + 1].y);
            pa[j][3] = h2u(s[2 * j + 1].z, s[2 * j + 1].w);
        }

        // ---- O += P @ V ----
#pragma unroll
        for (int kt = 0; kt < 4; kt++) {
            uint32_t vb[8][2];
#pragma unroll
            for (int q4 = 0; q4 < 4; q4++)
                ldsm4t(vb[2 * q4][0], vb[2 * q4][1], vb[2 * q4 + 1][0], vb[2 * q4 + 1][1],
                       &vs[(kt * 16 + arow) * AP + q4 * 16 + acol]);
#pragma unroll
            for (int nt = 0; nt < 8; nt++)
                mma_h(accO[nt], pa[kt][0], pa[kt][1], pa[kt][2], pa[kt][3],
                      vb[nt][0], vb[nt][1]);
        }
        st = (st + 1) % 3;
    }

    // one reduction at the end: combine tg lanes (cols) within each row
    l0 += __shfl_xor_sync(0xffffffffu, l0, 1);
    l0 += __shfl_xor_sync(0xffffffffu, l0, 2);
    l1 += __shfl_xor_sync(0xffffffffu, l1, 1);
    l1 += __shfl_xor_sync(0xffffffffu, l1, 2);

    const int b = bh / NH, h = bh % NH;
    const int r0 = qt * 128 + w * 16 + g;
    const float i0 = 1.f / l0, i1 = 1.f / l1;
#pragma unroll
    for (int nt = 0; nt < 8; nt++) {
        int col = h * 64 + nt * 8 + 2 * tg;
        *(uint32_t*)(outh + (size_t)(b * NSEQ + r0) * DIMC + col) =
            h2u(accO[nt].x * i0, accO[nt].y * i0);
        *(uint32_t*)(outh + (size_t)(b * NSEQ + r0 + 8) * DIMC + col) =
            h2u(accO[nt].z * i1, accO[nt].w * i1);
    }
}

// ---------------- launch ----------------------------------------------------
extern "C" void kernel_launch(void* const* d_in, const int* in_sizes, int n_in,
                              void* d_out, int out_size)
{
    (void)in_sizes; (void)n_in; (void)out_size;
    const float* x         = (const float*)d_in[0];
    const float* positions = (const float*)d_in[1];
    const float* qkv_w     = (const float*)d_in[2];
    const float* proj_w    = (const float*)d_in[3];
    const float* proj_b    = (const float*)d_in[4];
    const float* qn_w      = (const float*)d_in[5];
    const float* kn_w      = (const float*)d_in[6];
    float* out = (float*)d_out;

    float *qkv;
    __half *xh, *qkvwh, *projwh, *atth, *q, *k, *v;
    cudaGetSymbolAddress((void**)&qkv,    g_qkv);
    cudaGetSymbolAddress((void**)&xh,     g_xh);
    cudaGetSymbolAddress((void**)&qkvwh,  g_qkvwh);
    cudaGetSymbolAddress((void**)&projwh, g_projwh);
    cudaGetSymbolAddress((void**)&atth,   g_atth);
    cudaGetSymbolAddress((void**)&q,      g_q);
    cudaGetSymbolAddress((void**)&k,      g_k);
    cudaGetSymbolAddress((void**)&v,      g_v);

    const int attn_smem = (128 * AP + 6 * KVTILE) * (int)sizeof(__half);  // 73728
    cudaFuncSetAttribute(gemm_h<false>,
                         cudaFuncAttributeMaxDynamicSharedMemorySize, GEMM_SMEM);
    cudaFuncSetAttribute(gemm_h<true>,
                         cudaFuncAttributeMaxDynamicSharedMemorySize, GEMM_SMEM);
    cudaFuncSetAttribute(attn_h,
                         cudaFuncAttributeMaxDynamicSharedMemorySize, attn_smem);

    // 0) convert inputs to fp16
    {
        int n4;
        n4 = MROWS * DIMC / 4;
        f2h_kernel<<<(n4 + 255) / 256, 256>>>(x, xh, n4);
        n4 = 3 * DIMC * DIMC / 4;
        f2h_kernel<<<(n4 + 255) / 256, 256>>>(qkv_w, qkvwh, n4);
        n4 = DIMC * DIMC / 4;
        f2h_kernel<<<(n4 + 255) / 256, 256>>>(proj_w, projwh, n4);
    }

    // 1) qkv = x @ qkv_w^T    [4096, 2304] (fp32 out)
    gemm_h<false><<<dim3(2304 / 256, MROWS / 128), 256, GEMM_SMEM>>>(
        xh, qkvwh, nullptr, qkv, MROWS, 3 * DIMC, DIMC);

    // 2) rmsnorm + rope + scale + fp16 + transpose to [BH, N, DH]
    prep_kernel<<<(MROWS * NH * 32) / 256, 256>>>(
        qkv, positions, qn_w, kn_w, q, k, v);

    // 3) attention (fp16 tensor cores, static-offset base-2 softmax)
    attn_h<<<dim3(NSEQ / 128, BHN), 256, attn_smem>>>(q, k, v, atth);

    // 4) out = att @ proj_w^T + proj_b
    gemm_h<true><<<dim3(DIMC / 256, MROWS / 128), 256, GEMM_SMEM>>>(
        atth, projwh, proj_b, out, MROWS, DIMC, DIMC);
}

// round 10
// speedup vs baseline: 1.0001x; 1.0001x over previous
#include <cuda_runtime.h>
#include <cuda_fp16.h>
#include <math.h>
#include <stdint.h>

#define BB 2
#define NSEQ 2048
#define DIMC 768
#define NH 12
#define DH 64
#define BHN (BB*NH)
#define MROWS (BB*NSEQ)
// 0.125 * log2(e): softmax done in base-2
#define QSCALE_L2E 0.18033688011112042f
// static softmax offset: |scores| <= 64*0.125*log2e = 11.54 < 12 (rmsnorm + rotation)
#define SOFF 12.0f

// ---------------- scratch (static device globals; no allocation) -------------
__device__ float  g_qkv[(size_t)MROWS * 3 * DIMC];          // fp32 qkv
__device__ __half g_xh[(size_t)MROWS * DIMC];
__device__ __half g_qkvwh[(size_t)3 * DIMC * DIMC];
__device__ __half g_projwh[(size_t)DIMC * DIMC];
__device__ __half g_atth[(size_t)MROWS * DIMC];
__device__ __half g_q[(size_t)BHN * NSEQ * DH];
__device__ __half g_k[(size_t)BHN * NSEQ * DH];
__device__ __half g_v[(size_t)BHN * NSEQ * DH];

// ---------------- helpers ---------------------------------------------------
__device__ __forceinline__ uint32_t h2u(float a, float b) {
    __half2 h = __floats2half2_rn(a, b);
    return *reinterpret_cast<uint32_t*>(&h);
}
__device__ __forceinline__ uint32_t smaddr(const void* p) {
    return (uint32_t)__cvta_generic_to_shared(p);
}
__device__ __forceinline__ void cp16(void* dst, const void* src) {
    asm volatile("cp.async.cg.shared.global [%0], [%1], 16;"
                 :: "r"(smaddr(dst)), "l"(src));
}
#define CP_COMMIT() asm volatile("cp.async.commit_group;")
#define CP_WAIT(n)  asm volatile("cp.async.wait_group %0;" :: "n"(n))

__device__ __forceinline__ void ldsm4(uint32_t& r0, uint32_t& r1,
                                      uint32_t& r2, uint32_t& r3, const void* p) {
    asm volatile("ldmatrix.sync.aligned.m8n8.x4.shared.b16 {%0,%1,%2,%3}, [%4];"
                 : "=r"(r0), "=r"(r1), "=r"(r2), "=r"(r3) : "r"(smaddr(p)));
}
__device__ __forceinline__ void ldsm4t(uint32_t& r0, uint32_t& r1,
                                       uint32_t& r2, uint32_t& r3, const void* p) {
    asm volatile("ldmatrix.sync.aligned.m8n8.x4.trans.shared.b16 {%0,%1,%2,%3}, [%4];"
                 : "=r"(r0), "=r"(r1), "=r"(r2), "=r"(r3) : "r"(smaddr(p)));
}
__device__ __forceinline__ void mma_h(float4& d,
    uint32_t a0, uint32_t a1, uint32_t a2, uint32_t a3,
    uint32_t b0, uint32_t b1)
{
    asm volatile(
        "mma.sync.aligned.m16n8k16.row.col.f32.f16.f16.f32 "
        "{%0,%1,%2,%3}, {%4,%5,%6,%7}, {%8,%9}, {%0,%1,%2,%3};"
        : "+f"(d.x), "+f"(d.y), "+f"(d.z), "+f"(d.w)
        : "r"(a0), "r"(a1), "r"(a2), "r"(a3), "r"(b0), "r"(b1));
}

// exp2 via FMA polynomial + exponent splice — no MUFU in the hot loop.
__device__ __forceinline__ float exp2_fast(float t) {
    t = fmaxf(t, -120.0f);
    float z = t + 12582912.0f;
    int  i = __float_as_int(z) - 0x4B400000;
    float f = t - (z - 12582912.0f);
    float p = 1.3333558e-3f;
    p = fmaf(p, f, 9.6181291e-3f);
    p = fmaf(p, f, 5.5504109e-2f);
    p = fmaf(p, f, 2.4022651e-1f);
    p = fmaf(p, f, 6.9314718e-1f);
    p = fmaf(p, f, 1.0f);
    return __int_as_float((i + 127) << 23) * p;
}

// ---------------- fp32 -> fp16 convert --------------------------------------
__global__ void __launch_bounds__(256) f2h_kernel(const float* __restrict__ in,
                                                  __half* __restrict__ out, int n4)
{
    int i = blockIdx.x * blockDim.x + threadIdx.x;
    if (i >= n4) return;
    float4 v = *(const float4*)(in + (size_t)i * 4);
    uint2 o;
    o.x = h2u(v.x, v.y);
    o.y = h2u(v.z, v.w);
    *(uint2*)(out + (size_t)i * 4) = o;
}

// ---------------- fp16 GEMM: C[m][n] = sum_k A[m][k] * W[n][k] (+bias) ------
// CTA tile 128x256, BK=32, 256 threads (8 warps, 2m x 4n), warp tile 64x64.
// 3-stage cp.async pipeline, one barrier per iteration, ldmatrix fragments.
#define GP 40
#define GATILE (128 * GP)
#define GBTILE (256 * GP)
#define GEMM_SMEM ((3 * GATILE + 3 * GBTILE) * (int)sizeof(__half))   // 92160
template<bool BIAS>
__global__ void __launch_bounds__(256) gemm_h(
    const __half* __restrict__ A, const __half* __restrict__ W,
    const float* __restrict__ bias, float* __restrict__ C,
    int M, int N, int K)
{
    extern __shared__ __half gsm[];
    __half* As = gsm;                  // 3 stages x GATILE
    __half* Ws = gsm + 3 * GATILE;     // 3 stages x GBTILE

    const int tid = threadIdx.x;
    const int lane = tid & 31, wid = tid >> 5;
    const int g = lane >> 2, tg = lane & 3;
    const int wm = (wid & 1) * 64;
    const int wn = (wid >> 1) * 64;
    const int mtile = blockIdx.y * 128, ntile = blockIdx.x * 256;

    const int ldr = tid >> 2;            // 0..63
    const int ldc = (tid & 3) * 8;       // 0,8,16,24

    auto issue = [&](int k0, int st) {
#pragma unroll
        for (int i = 0; i < 2; i++) {      // A: 128 rows
            int r = ldr + i * 64;
            cp16(&As[st * GATILE + r * GP + ldc], A + (size_t)(mtile + r) * K + k0 + ldc);
        }
#pragma unroll
        for (int i = 0; i < 4; i++) {      // B: 256 rows
            int r = ldr + i * 64;
            cp16(&Ws[st * GBTILE + r * GP + ldc], W + (size_t)(ntile + r) * K + k0 + ldc);
        }
        CP_COMMIT();
    };

    issue(0, 0);
    issue(32, 1);

    float4 acc[4][8];
#pragma unroll
    for (int mt = 0; mt < 4; mt++)
#pragma unroll
        for (int nt = 0; nt < 8; nt++) acc[mt][nt] = make_float4(0.f, 0.f, 0.f, 0.f);

    const int NIT = K / 32;
    const int arow = (lane & 15);
    const int acol = ((lane >> 4) & 1) * 8;
    const int brow = ((lane & 16) >> 1) + (lane & 7);
    const int bcol = (lane & 8);

    int st = 0;
    for (int it = 0; it < NIT; it++) {
        if (it == NIT - 1) { CP_WAIT(0); } else { CP_WAIT(1); }
        __syncthreads();
        if (it + 2 < NIT) issue((it + 2) * 32, (st + 2) % 3);
        const __half* as = As + st * GATILE;
        const __half* ws = Ws + st * GBTILE;
#pragma unroll
        for (int ks = 0; ks < 2; ks++) {
            uint32_t af[4][4], bf[8][2];
#pragma unroll
            for (int mt = 0; mt < 4; mt++)
                ldsm4(af[mt][0], af[mt][1], af[mt][2], af[mt][3],
                      &as[(wm + mt * 16 + arow) * GP + ks * 16 + acol]);
#pragma unroll
            for (int p = 0; p < 4; p++)
                ldsm4(bf[2 * p][0], bf[2 * p][1], bf[2 * p + 1][0], bf[2 * p + 1][1],
                      &ws[(wn + p * 16 + brow) * GP + ks * 16 + bcol]);
#pragma unroll
            for (int mt = 0; mt < 4; mt++)
#pragma unroll
                for (int nt = 0; nt < 8; nt++)
                    mma_h(acc[mt][nt], af[mt][0], af[mt][1], af[mt][2], af[mt][3],
                          bf[nt][0], bf[nt][1]);
        }
        st = (st + 1) % 3;
    }

#pragma unroll
    for (int mt = 0; mt < 4; mt++) {
        int r0 = mtile + wm + mt * 16 + g;
#pragma unroll
        for (int nt = 0; nt < 8; nt++) {
            int col = ntile + wn + nt * 8 + 2 * tg;
            float4 v = acc[mt][nt];
            float b0v = 0.f, b1v = 0.f;
            if (BIAS) { b0v = bias[col]; b1v = bias[col + 1]; }
            float2 t0 = {v.x + b0v, v.y + b1v};
            float2 t1 = {v.z + b0v, v.w + b1v};
            *(float2*)(C + (size_t)r0 * N + col) = t0;
            *(float2*)(C + (size_t)(r0 + 8) * N + col) = t1;
        }
    }
}

// -------- fused rmsnorm + 3D RoPE + q-scale(log2e) + fp16 + transpose -------
__global__ void __launch_bounds__(256) prep_kernel(
    const float* __restrict__ qkv, const float* __restrict__ positions,
    const float* __restrict__ qn_w, const float* __restrict__ kn_w,
    __half* __restrict__ qT, __half* __restrict__ kT, __half* __restrict__ vT)
{
    int gwarp = (blockIdx.x * blockDim.x + threadIdx.x) >> 5;
    int lane  = threadIdx.x & 31;
    if (gwarp >= MROWS * NH) return;
    int h = gwarp % NH;
    int m = gwarp / NH;
    int b = m / NSEQ;
    int t = m % NSEQ;

    const float* row = qkv + (size_t)m * (3 * DIMC) + h * DH;
    float2 q = *(const float2*)(row + 2 * lane);
    float2 k = *(const float2*)(row + DIMC + 2 * lane);
    float2 v = *(const float2*)(row + 2 * DIMC + 2 * lane);

    float sq = q.x * q.x + q.y * q.y;
    float sk = k.x * k.x + k.y * k.y;
#pragma unroll
    for (int off = 16; off; off >>= 1) {
        sq += __shfl_xor_sync(0xffffffffu, sq, off);
        sk += __shfl_xor_sync(0xffffffffu, sk, off);
    }
    float rq = rsqrtf(sq * (1.0f / 64.0f) + 1e-6f);
    float rk = rsqrtf(sk * (1.0f / 64.0f) + 1e-6f);
    float2 wq = *(const float2*)(qn_w + 2 * lane);
    float2 wk = *(const float2*)(kn_w + 2 * lane);
    q.x *= rq * wq.x; q.y *= rq * wq.y;
    k.x *= rk * wk.x; k.y *= rk * wk.y;

    if (lane < 30) {                   // rope pairs: first 60 dims
        int p = lane / 10;
        int f = lane % 10;
        float pos  = positions[(size_t)m * 3 + p];
        float freq = __expf(-0.92103403719761836f * (float)f);  // 10000^(-f/10)
        float ang  = pos * freq;
        float s, c;
        __sincosf(ang, &s, &c);
        float qe = q.x * c - q.y * s, qo = q.x * s + q.y * c;
        float ke = k.x * c - k.y * s, ko = k.x * s + k.y * c;
        q.x = qe; q.y = qo; k.x = ke; k.y = ko;
    }
    q.x *= QSCALE_L2E; q.y *= QSCALE_L2E;

    size_t o = ((size_t)(b * NH + h) * NSEQ + t) * DH + 2 * lane;
    *(uint32_t*)(qT + o) = h2u(q.x, q.y);
    *(uint32_t*)(kT + o) = h2u(k.x, k.y);
    *(uint32_t*)(vT + o) = h2u(v.x, v.y);
}

// ---------------- fp16 flash-attention (static-offset base-2 softmax) -------
// 256 threads (8 warps); warp owns 16 query rows. Br=128, Bc=64, DH=64.
// Scores are bounded (rmsnorm -> |s| <= 11.54 base-2), so softmax uses a fixed
// offset: no running max, no correction factors, no per-iter reductions.
#define AP 72
#define KVTILE (64 * AP)
__global__ void __launch_bounds__(256) attn_h(
    const __half* __restrict__ qT, const __half* __restrict__ kT,
    const __half* __restrict__ vT, __half* __restrict__ outh)
{
    extern __shared__ __half asm_[];
    __half* Qs = asm_;                    // 128 x AP
    __half* Ks = asm_ + 128 * AP;         // 3 stages x 64 x AP
    __half* Vs = Ks + 3 * KVTILE;         // 3 stages x 64 x AP

    const int tid = threadIdx.x, lane = tid & 31, w = tid >> 5;
    const int g = lane >> 2, tg = lane & 3;
    const int qt = blockIdx.x, bh = blockIdx.y;

    auto issue_kv = [&](int kc, int st) {
        const __half* kb = kT + ((size_t)bh * NSEQ + kc * 64) * DH;
        const __half* vb = vT + ((size_t)bh * NSEQ + kc * 64) * DH;
#pragma unroll
        for (int i = 0; i < 2; i++) {
            int idx = tid + i * 256;
            int r = idx >> 3, c = (idx & 7) * 8;
            cp16(&Ks[st * KVTILE + r * AP + c], kb + r * 64 + c);
            cp16(&Vs[st * KVTILE + r * AP + c], vb + r * 64 + c);
        }
        CP_COMMIT();
    };

    const __half* qb = qT + ((size_t)bh * NSEQ + qt * 128) * DH;
#pragma unroll
    for (int i = 0; i < 4; i++) {
        int idx = tid + i * 256;
        int r = idx >> 3, c = (idx & 7) * 8;
        *(uint4*)&Qs[r * AP + c] = *(const uint4*)(qb + r * 64 + c);
    }

    issue_kv(0, 0);
    issue_kv(1, 1);
    __syncthreads();

    const int arow = (lane & 15);
    const int acol = ((lane >> 4) & 1) * 8;
    const int brow = ((lane & 16) >> 1) + (lane & 7);
    const int bcol = (lane & 8);

    uint32_t qa[4][4];
#pragma unroll
    for (int kt = 0; kt < 4; kt++)
        ldsm4(qa[kt][0], qa[kt][1], qa[kt][2], qa[kt][3],
              &Qs[(w * 16 + arow) * AP + kt * 16 + acol]);

    float4 accO[8];
#pragma unroll
    for (int nt = 0; nt < 8; nt++) accO[nt] = make_float4(0.f, 0.f, 0.f, 0.f);
    float l0 = 0.f, l1 = 0.f;

    int st = 0;
    for (int kc = 0; kc < 32; kc++) {
        if (kc == 31) { CP_WAIT(0); } else { CP_WAIT(1); }
        __syncthreads();
        if (kc + 2 < 32) issue_kv(kc + 2, (st + 2) % 3);
        const __half* ks = Ks + st * KVTILE;
        const __half* vs = Vs + st * KVTILE;

        // ---- S = Q @ K^T ----
        float4 s[8];
#pragma unroll
        for (int nt = 0; nt < 8; nt++) s[nt] = make_float4(0.f, 0.f, 0.f, 0.f);
#pragma unroll
        for (int kt = 0; kt < 4; kt++) {
            uint32_t kb[8][2];
#pragma unroll
            for (int p = 0; p < 4; p++)
                ldsm4(kb[2 * p][0], kb[2 * p][1], kb[2 * p + 1][0], kb[2 * p + 1][1],
                      &ks[(p * 16 + brow) * AP + kt * 16 + bcol]);
#pragma unroll
            for (int nt = 0; nt < 8; nt++)
                mma_h(s[nt], qa[kt][0], qa[kt][1], qa[kt][2], qa[kt][3],
                      kb[nt][0], kb[nt][1]);
        }

        // ---- static-offset softmax: p = 2^(s - SOFF) ----
        uint32_t pa[4][4];
#pragma unroll
        for (int nt = 0; nt < 8; nt++) {
            s[nt].x = exp2_fast(s[nt].x - SOFF);
            s[nt].y = exp2_fast(s[nt].y - SOFF);
            s[nt].z = exp2_fast(s[nt].z - SOFF);
            s[nt].w = exp2_fast(s[nt].w - SOFF);
            l0 += s[nt].x + s[nt].y;
            l1 += s[nt].z + s[nt].w;
        }
#pragma unroll
        for (int j = 0; j < 4; j++) {
            pa[j][0] = h2u(s[2 * j].x,     s[2 * j].y);
            pa[j][1] = h2u(s[2 * j].z,     s[2 * j].w);
            pa[j][2] = h2u(s[2 * j + 1].x, s[2 * j + 1].y);
            pa[j][3] = h2u(s[2 * j + 1].z, s[2 * j + 1].w);
        }

        // ---- O += P @ V ----
#pragma unroll
        for (int kt = 0; kt < 4; kt++) {
            uint32_t vb[8][2];
#pragma unroll
            for (int q4 = 0; q4 < 4; q4++)
                ldsm4t(vb[2 * q4][0], vb[2 * q4][1], vb[2 * q4 + 1][0], vb[2 * q4 + 1][1],
                       &vs[(kt * 16 + arow) * AP + q4 * 16 + acol]);
#pragma unroll
            for (int nt = 0; nt < 8; nt++)
                mma_h(accO[nt], pa[kt][0], pa[kt][1], pa[kt][2], pa[kt][3],
                      vb[nt][0], vb[nt][1]);
        }
        st = (st + 1) % 3;
    }

    // one reduction at the end: combine tg lanes (cols) within each row
    l0 += __shfl_xor_sync(0xffffffffu, l0, 1);
    l0 += __shfl_xor_sync(0xffffffffu, l0, 2);
    l1 += __shfl_xor_sync(0xffffffffu, l1, 1);
    l1 += __shfl_xor_sync(0xffffffffu, l1, 2);

    const int b = bh / NH, h = bh % NH;
    const int r0 = qt * 128 + w * 16 + g;
    const float i0 = 1.f / l0, i1 = 1.f / l1;
#pragma unroll
    for (int nt = 0; nt < 8; nt++) {
        int col = h * 64 + nt * 8 + 2 * tg;
        *(uint32_t*)(outh + (size_t)(b * NSEQ + r0) * DIMC + col) =
            h2u(accO[nt].x * i0, accO[nt].y * i0);
        *(uint32_t*)(outh + (size_t)(b * NSEQ + r0 + 8) * DIMC + col) =
            h2u(accO[nt].z * i1, accO[nt].w * i1);
    }
}

// ---------------- launch ----------------------------------------------------
extern "C" void kernel_launch(void* const* d_in, const int* in_sizes, int n_in,
                              void* d_out, int out_size)
{
    (void)in_sizes; (void)n_in; (void)out_size;
    const float* x         = (const float*)d_in[0];
    const float* positions = (const float*)d_in[1];
    const float* qkv_w     = (const float*)d_in[2];
    const float* proj_w    = (const float*)d_in[3];
    const float* proj_b    = (const float*)d_in[4];
    const float* qn_w      = (const float*)d_in[5];
    const float* kn_w      = (const float*)d_in[6];
    float* out = (float*)d_out;

    float *qkv;
    __half *xh, *qkvwh, *projwh, *atth, *q, *k, *v;
    cudaGetSymbolAddress((void**)&qkv,    g_qkv);
    cudaGetSymbolAddress((void**)&xh,     g_xh);
    cudaGetSymbolAddress((void**)&qkvwh,  g_qkvwh);
    cudaGetSymbolAddress((void**)&projwh, g_projwh);
    cudaGetSymbolAddress((void**)&atth,   g_atth);
    cudaGetSymbolAddress((void**)&q,      g_q);
    cudaGetSymbolAddress((void**)&k,      g_k);
    cudaGetSymbolAddress((void**)&v,      g_v);

    const int attn_smem = (128 * AP + 6 * KVTILE) * (int)sizeof(__half);  // 73728
    cudaFuncSetAttribute(gemm_h<false>,
                         cudaFuncAttributeMaxDynamicSharedMemorySize, GEMM_SMEM);
    cudaFuncSetAttribute(gemm_h<true>,
                         cudaFuncAttributeMaxDynamicSharedMemorySize, GEMM_SMEM);
    cudaFuncSetAttribute(attn_h,
                         cudaFuncAttributeMaxDynamicSharedMemorySize, attn_smem);

    // 0) convert inputs to fp16
    {
        int n4;
        n4 = MROWS * DIMC / 4;
        f2h_kernel<<<(n4 + 255) / 256, 256>>>(x, xh, n4);
        n4 = 3 * DIMC * DIMC / 4;
        f2h_kernel<<<(n4 + 255) / 256, 256>>>(qkv_w, qkvwh, n4);
        n4 = DIMC * DIMC / 4;
        f2h_kernel<<<(n4 + 255) / 256, 256>>>(proj_w, projwh, n4);
    }

    // 1) qkv = x @ qkv_w^T    [4096, 2304] (fp32 out)
    gemm_h<false><<<dim3(2304 / 256, MROWS / 128), 256, GEMM_SMEM>>>(
        xh, qkvwh, nullptr, qkv, MROWS, 3 * DIMC, DIMC);

    // 2) rmsnorm + rope + scale + fp16 + transpose to [BH, N, DH]
    prep_kernel<<<(MROWS * NH * 32) / 256, 256>>>(
        qkv, positions, qn_w, kn_w, q, k, v);

    // 3) attention (fp16 tensor cores, static-offset base-2 softmax)
    attn_h<<<dim3(NSEQ / 128, BHN), 256, attn_smem>>>(q, k, v, atth);

    // 4) out = att @ proj_w^T + proj_b
    gemm_h<true><<<dim3(DIMC / 256, MROWS / 128), 256, GEMM_SMEM>>>(
        atth, projwh, proj_b, out, MROWS, DIMC, DIMC);
}